// round 14
// baseline (speedup 1.0000x reference)
#include <cuda_runtime.h>
#include <cstdint>

#define Nn   262144
#define Ee   1048576
#define NCf  30
#define EDf  13
#define Hh   256
#define GHh  512
#define OUTC 256
#define Gg   8192

// ---------------- device scratch (no allocs allowed) ----------------
__device__ float g_hid [(size_t)Nn * Hh];
__device__ float g_hid2[(size_t)Nn * Hh];
__device__ float g_agg [(size_t)Nn * Hh];   // agg ping
__device__ float g_aggB[(size_t)Nn * Hh];   // agg pong
__device__ float g_Z   [(size_t)Gg * GHh];
__device__ float g_cnt [Gg];
__device__ int   g_b32 [Nn];
__device__ int   g_ei32[2 * Ee];
__device__ long long g_eis[2 * Ee];          // src-sorted indices, SAME dtype layout as ei
__device__ float g_ea_s[(size_t)Ee * EDf];   // edge_attr permuted to src-sorted order
__device__ int   g_perm [Ee];
__device__ int   g_hist [Nn];
__device__ int   g_cursor[Nn];
__device__ int   g_flags[2];   // [0]=edge_index is int64, [1]=batch is int64

// ---------------- helpers ----------------
__device__ __forceinline__ unsigned f2tf(float x) {
    unsigned r;
    asm("cvt.rna.tf32.f32 %0, %1;" : "=r"(r) : "f"(x));
    return r;
}
__device__ __forceinline__ void cpa16(float* s, const float* g) {
    unsigned sa = (unsigned)__cvta_generic_to_shared(s);
    asm volatile("cp.async.cg.shared.global [%0], [%1], 16;\n" :: "r"(sa), "l"(g));
}

// dtype detection: int64 little-endian high words (odd 32-bit indices) are 0 for
// values < 2^31; int32 payloads at the buffer tail are nonzero with ~certainty.
__global__ void detect_kernel(const unsigned* __restrict__ ei,
                              const unsigned* __restrict__ bt) {
    if (threadIdx.x == 0 && blockIdx.x == 0) {
        int is64 = 1;
        for (int i = 0; i < 8; i++)
            if (ei[2 * Ee - 1 - 2 * i] != 0u) is64 = 0;   // odd indices
        g_flags[0] = is64;
        int b64 = 1;
        for (int i = 0; i < 8; i++)
            if (bt[Nn - 1 - 2 * i] != 0u) b64 = 0;        // Nn-1 is odd
        g_flags[1] = b64;
    }
}

__global__ void zero_kernel(float4* __restrict__ p, int n4) {
    for (int i = blockIdx.x * blockDim.x + threadIdx.x; i < n4;
         i += gridDim.x * blockDim.x)
        p[i] = make_float4(0.f, 0.f, 0.f, 0.f);
}

// batch -> int32 (once per replay; cheap)
__global__ void b32_kernel(const void* __restrict__ batch) {
    const int is64 = g_flags[1];
    const long long* b64 = (const long long*)batch;
    const int*       b32 = (const int*)batch;
    for (int i = blockIdx.x * blockDim.x + threadIdx.x; i < Nn;
         i += gridDim.x * blockDim.x)
        g_b32[i] = is64 ? (int)b64[i] : b32[i];
}

// cnt[g] = |graph g| via binary search on sorted batch32
__global__ void cnt_kernel() {
    const int g = blockIdx.x * blockDim.x + threadIdx.x;
    if (g >= Gg) return;
    int lo = 0, hi = Nn;
    while (lo < hi) {
        int mid = (lo + hi) >> 1;
        if (g_b32[mid] < g) lo = mid + 1; else hi = mid;
    }
    const int start = lo;
    hi = Nn;
    while (lo < hi) {
        int mid = (lo + hi) >> 1;
        if (g_b32[mid] < g + 1) lo = mid + 1; else hi = mid;
    }
    g_cnt[g] = (float)(lo - start);
}

// ---------------- src-sort preprocessing (counting sort, every replay) ----
__global__ void conv_ei_kernel(const void* __restrict__ ei) {
    const int is64 = g_flags[0];
    const long long* e64 = (const long long*)ei;
    const int*       e32 = (const int*)ei;
    for (int i = blockIdx.x * blockDim.x + threadIdx.x; i < 2 * Ee;
         i += gridDim.x * blockDim.x)
        g_ei32[i] = is64 ? (int)e64[i] : e32[i];
}
__global__ void hist_zero_kernel() {
    for (int i = blockIdx.x * blockDim.x + threadIdx.x; i < Nn;
         i += gridDim.x * blockDim.x)
        g_hist[i] = 0;
}
__global__ void hist_kernel() {   // histogram over SRC (gather locality)
    for (int e = blockIdx.x * blockDim.x + threadIdx.x; e < Ee;
         e += gridDim.x * blockDim.x)
        atomicAdd(&g_hist[g_ei32[e]], 1);
}
// single block, 1024 threads: thread t owns nodes [t*256, (t+1)*256)
__global__ void scan_kernel() {
    __shared__ int sh[1024];
    const int t = threadIdx.x;
    const int base = t * 256;
    int sum = 0;
    for (int i = 0; i < 256; i++) sum += g_hist[base + i];
    sh[t] = sum;
    __syncthreads();
    for (int off = 1; off < 1024; off <<= 1) {
        int v = sh[t];
        int o = (t >= off) ? sh[t - off] : 0;
        __syncthreads();
        sh[t] = v + o;
        __syncthreads();
    }
    int run = sh[t] - sum;   // exclusive base
    for (int i = 0; i < 256; i++) {
        g_cursor[base + i] = run;
        run += g_hist[base + i];
    }
}
// write sorted (src,dst) pairs in the SAME dtype layout the edge kernel expects
__global__ void scatter_kernel() {
    const int is64 = g_flags[0];
    long long* o64 = g_eis;
    int*       o32 = (int*)g_eis;
    for (int e = blockIdx.x * blockDim.x + threadIdx.x; e < Ee;
         e += gridDim.x * blockDim.x) {
        int s = g_ei32[e];
        int d = g_ei32[Ee + e];
        int pos = atomicAdd(&g_cursor[s], 1);
        if (is64) { o64[pos] = s; o64[Ee + pos] = d; }
        else      { o32[pos] = s; o32[Ee + pos] = d; }
        g_perm[pos] = e;
    }
}
__global__ void ea_copy_kernel(const float* __restrict__ ea) {
    for (int pos = blockIdx.x * blockDim.x + threadIdx.x; pos < Ee;
         pos += gridDim.x * blockDim.x) {
        int e = g_perm[pos];
        const float* s = ea + (size_t)e * EDf;
        float* d = g_ea_s + (size_t)pos * EDf;
#pragma unroll
        for (int k = 0; k < EDf; k++) d[k] = s[k];
    }
}

// ==================================================================
// Pipelined tf32 GEMM: 2-stage cp.async double buffer. Single A operand.
// C[M,Nc] = relu?(A @ B + bias). lda == K, K % 32 == 0.
// CTA tile 128x128, 8 warps. x = N-tile (fast), y = M-tile.
// SEED: also store the epilogue values into zbuf (seeds next layer's agg).
// POOL: red.add the values into Z[batch32[row]*Nc+col] instead of storing C.
// ==================================================================
template <bool SEED, bool RELU, bool POOL>
__global__ __launch_bounds__(256, 2)
void gemm_pipe(const float* __restrict__ A, const float* __restrict__ B,
               const float* __restrict__ bias, float* __restrict__ C,
               float* __restrict__ zbuf, int M, int Nc, int K)
{
    extern __shared__ float sm[];
    float* As = sm;                  // 2 * 4608
    float* Bs = sm + 2 * 4608;       // 2 * 4224

    const int tid   = threadIdx.x;
    const int lane  = tid & 31;
    const int warp  = tid >> 5;
    const int tq    = lane & 3;
    const int gq    = lane >> 2;
    const int warpM = (warp & 3) * 32;
    const int warpN = (warp >> 2) * 64;
    const int blockM = blockIdx.y * 128;
    const int blockN = blockIdx.x * 128;

    float acc[2][8][4];
#pragma unroll
    for (int mt = 0; mt < 2; mt++)
#pragma unroll
        for (int nt = 0; nt < 8; nt++)
#pragma unroll
            for (int j = 0; j < 4; j++) acc[mt][nt][j] = 0.f;

    auto issue = [&](int k0, int st) {
#pragma unroll
        for (int i = 0; i < 4; i++) {
            int idx = tid + i * 256;
            int row = idx >> 3;
            int c   = (idx & 7) * 4;
            cpa16(As + st * 4608 + row * 36 + c,
                  A + (size_t)(blockM + row) * K + k0 + c);
        }
#pragma unroll
        for (int i = 0; i < 4; i++) {
            int idx = tid + i * 256;
            int row = idx >> 5;
            int c   = (idx & 31) * 4;
            cpa16(Bs + st * 4224 + row * 132 + c,
                  B + (size_t)(k0 + row) * Nc + blockN + c);
        }
        asm volatile("cp.async.commit_group;\n" ::: "memory");
    };

    const int nIter = K >> 5;
    issue(0, 0);

    for (int it = 0; it < nIter; it++) {
        const int st = it & 1;
        if (it + 1 < nIter) {
            issue((it + 1) << 5, st ^ 1);
            asm volatile("cp.async.wait_group 1;\n" ::: "memory");
        } else {
            asm volatile("cp.async.wait_group 0;\n" ::: "memory");
        }
        __syncthreads();

        const float* as = As + st * 4608;
        const float* bs = Bs + st * 4224;
#pragma unroll
        for (int kk = 0; kk < 32; kk += 8) {
            unsigned a[2][4], b[8][2];
#pragma unroll
            for (int mt = 0; mt < 2; mt++) {
                int r = warpM + mt * 16 + gq;
                a[mt][0] = f2tf(as[(r)     * 36 + kk + tq]);
                a[mt][1] = f2tf(as[(r + 8) * 36 + kk + tq]);
                a[mt][2] = f2tf(as[(r)     * 36 + kk + tq + 4]);
                a[mt][3] = f2tf(as[(r + 8) * 36 + kk + tq + 4]);
            }
#pragma unroll
            for (int nt = 0; nt < 8; nt++) {
                int cidx = warpN + nt * 8 + gq;
                b[nt][0] = f2tf(bs[(kk + tq)     * 132 + cidx]);
                b[nt][1] = f2tf(bs[(kk + tq + 4) * 132 + cidx]);
            }
#pragma unroll
            for (int mt = 0; mt < 2; mt++)
#pragma unroll
                for (int nt = 0; nt < 8; nt++)
                    asm volatile(
                        "mma.sync.aligned.m16n8k8.row.col.f32.tf32.tf32.f32 "
                        "{%0,%1,%2,%3},{%4,%5,%6,%7},{%8,%9},{%0,%1,%2,%3};"
                        : "+f"(acc[mt][nt][0]), "+f"(acc[mt][nt][1]),
                          "+f"(acc[mt][nt][2]), "+f"(acc[mt][nt][3])
                        : "r"(a[mt][0]), "r"(a[mt][1]), "r"(a[mt][2]),
                          "r"(a[mt][3]), "r"(b[nt][0]), "r"(b[nt][1]));
        }
        __syncthreads();
    }

#pragma unroll
    for (int mt = 0; mt < 2; mt++) {
        int r0 = blockM + warpM + mt * 16 + gq;
        int r1 = r0 + 8;
        int zg0 = 0, zg1 = 0;
        if (POOL) { zg0 = g_b32[r0]; zg1 = g_b32[r1]; }
#pragma unroll
        for (int nt = 0; nt < 8; nt++) {
            int col = blockN + warpN + nt * 8 + 2 * tq;
            float b0 = bias[col], b1 = bias[col + 1];
            float v0 = acc[mt][nt][0] + b0, v1 = acc[mt][nt][1] + b1;
            float v2 = acc[mt][nt][2] + b0, v3 = acc[mt][nt][3] + b1;
            if (RELU) {
                v0 = fmaxf(v0, 0.f); v1 = fmaxf(v1, 0.f);
                v2 = fmaxf(v2, 0.f); v3 = fmaxf(v3, 0.f);
            }
            if (POOL) {
                float* q0 = g_Z + (size_t)zg0 * GHh + col;
                float* q1 = g_Z + (size_t)zg1 * GHh + col;
                asm volatile("red.global.add.v2.f32 [%0], {%1,%2};"
                             :: "l"(q0), "f"(v0), "f"(v1) : "memory");
                asm volatile("red.global.add.v2.f32 [%0], {%1,%2};"
                             :: "l"(q1), "f"(v2), "f"(v3) : "memory");
            } else {
                *(float2*)(C + (size_t)r0 * Nc + col) = make_float2(v0, v1);
                *(float2*)(C + (size_t)r1 * Nc + col) = make_float2(v2, v3);
                if (SEED) {
                    *(float2*)(zbuf + (size_t)r0 * Nc + col) = make_float2(v0, v1);
                    *(float2*)(zbuf + (size_t)r1 * Nc + col) = make_float2(v2, v3);
                }
            }
        }
    }
}

// ==================================================================
// Single-buffered tf32 GEMM — embed (K=30, unaligned rows; SEED seeds aggA
// with hid) and the final small GEMM (CNTB).
// x = N-tile, y = M-tile.
// ==================================================================
template <bool RELU, bool CNTB, bool SEED>
__global__ __launch_bounds__(256)
void gemm_tf32(const float* __restrict__ A, const float* __restrict__ B,
               const float* __restrict__ bias, const float* __restrict__ cnt,
               float* __restrict__ C, float* __restrict__ zbuf,
               int M, int Nc, int K, int lda)
{
    __shared__ unsigned As[128][36];
    __shared__ unsigned Bs[32][132];

    const int tid   = threadIdx.x;
    const int lane  = tid & 31;
    const int warp  = tid >> 5;
    const int tq    = lane & 3;
    const int gq    = lane >> 2;
    const int warpM = (warp & 3) * 32;
    const int warpN = (warp >> 2) * 64;
    const int blockM = blockIdx.y * 128;
    const int blockN = blockIdx.x * 128;

    float acc[2][8][4];
#pragma unroll
    for (int mt = 0; mt < 2; mt++)
#pragma unroll
        for (int nt = 0; nt < 8; nt++)
#pragma unroll
            for (int j = 0; j < 4; j++) acc[mt][nt][j] = 0.f;

    for (int k0 = 0; k0 < K; k0 += 32) {
        __syncthreads();
        const bool v4 = ((lda & 3) == 0) && (k0 + 32 <= K);
#pragma unroll
        for (int i = 0; i < 4; i++) {
            int row = (tid >> 3) + i * 32;
            int kq  = (tid & 7) * 4;
            size_t base = (size_t)(blockM + row) * lda + k0 + kq;
            float v0, v1, v2, v3;
            if (v4) {
                float4 tv = *(const float4*)(A + base);
                v0 = tv.x; v1 = tv.y; v2 = tv.z; v3 = tv.w;
            } else {
                v0 = (k0 + kq + 0 < K) ? A[base + 0] : 0.f;
                v1 = (k0 + kq + 1 < K) ? A[base + 1] : 0.f;
                v2 = (k0 + kq + 2 < K) ? A[base + 2] : 0.f;
                v3 = (k0 + kq + 3 < K) ? A[base + 3] : 0.f;
            }
            As[row][kq + 0] = f2tf(v0);
            As[row][kq + 1] = f2tf(v1);
            As[row][kq + 2] = f2tf(v2);
            As[row][kq + 3] = f2tf(v3);
        }
#pragma unroll
        for (int i = 0; i < 4; i++) {
            int kr = (tid >> 5) + i * 8;
            int n4 = (tid & 31) * 4;
            float4 tv = make_float4(0.f, 0.f, 0.f, 0.f);
            if (k0 + kr < K)
                tv = *(const float4*)(B + (size_t)(k0 + kr) * Nc + blockN + n4);
            Bs[kr][n4 + 0] = f2tf(tv.x);
            Bs[kr][n4 + 1] = f2tf(tv.y);
            Bs[kr][n4 + 2] = f2tf(tv.z);
            Bs[kr][n4 + 3] = f2tf(tv.w);
        }
        __syncthreads();
#pragma unroll
        for (int kk = 0; kk < 32; kk += 8) {
            unsigned a[2][4], b[8][2];
#pragma unroll
            for (int mt = 0; mt < 2; mt++) {
                int r = warpM + mt * 16;
                a[mt][0] = As[r + gq][kk + tq];
                a[mt][1] = As[r + gq + 8][kk + tq];
                a[mt][2] = As[r + gq][kk + tq + 4];
                a[mt][3] = As[r + gq + 8][kk + tq + 4];
            }
#pragma unroll
            for (int nt = 0; nt < 8; nt++) {
                int cidx = warpN + nt * 8 + gq;
                b[nt][0] = Bs[kk + tq][cidx];
                b[nt][1] = Bs[kk + tq + 4][cidx];
            }
#pragma unroll
            for (int mt = 0; mt < 2; mt++)
#pragma unroll
                for (int nt = 0; nt < 8; nt++)
                    asm volatile(
                        "mma.sync.aligned.m16n8k8.row.col.f32.tf32.tf32.f32 "
                        "{%0,%1,%2,%3},{%4,%5,%6,%7},{%8,%9},{%0,%1,%2,%3};"
                        : "+f"(acc[mt][nt][0]), "+f"(acc[mt][nt][1]),
                          "+f"(acc[mt][nt][2]), "+f"(acc[mt][nt][3])
                        : "r"(a[mt][0]), "r"(a[mt][1]), "r"(a[mt][2]),
                          "r"(a[mt][3]), "r"(b[nt][0]), "r"(b[nt][1]));
        }
    }
#pragma unroll
    for (int mt = 0; mt < 2; mt++) {
        int r0 = blockM + warpM + mt * 16 + gq;
        int r1 = r0 + 8;
        float cn0 = 0.f, cn1 = 0.f;
        if (CNTB) { cn0 = cnt[r0]; cn1 = cnt[r1]; }
#pragma unroll
        for (int nt = 0; nt < 8; nt++) {
            int col = blockN + warpN + nt * 8 + 2 * tq;
            float b0 = bias[col], b1 = bias[col + 1];
            float v0 = acc[mt][nt][0], v1 = acc[mt][nt][1];
            float v2 = acc[mt][nt][2], v3 = acc[mt][nt][3];
            if (CNTB) { v0 += cn0 * b0; v1 += cn0 * b1; v2 += cn1 * b0; v3 += cn1 * b1; }
            else      { v0 += b0;       v1 += b1;       v2 += b0;       v3 += b1; }
            if (RELU) {
                v0 = fmaxf(v0, 0.f); v1 = fmaxf(v1, 0.f);
                v2 = fmaxf(v2, 0.f); v3 = fmaxf(v3, 0.f);
            }
            *(float2*)(C + (size_t)r0 * Nc + col) = make_float2(v0, v1);
            *(float2*)(C + (size_t)r1 * Nc + col) = make_float2(v2, v3);
            if (SEED) {
                *(float2*)(zbuf + (size_t)r0 * Nc + col) = make_float2(v0, v1);
                *(float2*)(zbuf + (size_t)r1 * Nc + col) = make_float2(v2, v3);
            }
        }
    }
}

// ==================================================================
// Edge kernel — EXACT R13 source (frozen; proven 423us/layer): 64-col passes
// (gridDim.y=4), float2 weight bank, 2 edges per warp-iter, is64 selects.
// e = ea@We[l]+be[l]; msg = relu(hid[src]+e); red.add.v2 into agg[dst].
// agg is pre-seeded with hid, so after this kernel agg = hid + sum(msg).
// ==================================================================
__global__ __launch_bounds__(256)
void edge_kernel(const float* __restrict__ ea, const void* __restrict__ ei,
                 const float* __restrict__ We_l, const float* __restrict__ be_l,
                 const float* __restrict__ hid, float* __restrict__ agg)
{
    __shared__ float s_ea[128 * EDf];
    __shared__ int   s_src[128], s_dst[128];

    const int tid  = threadIdx.x;
    const int lane = tid & 31;
    const int warp = tid >> 5;
    const int colb = blockIdx.y * 64 + lane * 2;

    float2 w[EDf];
#pragma unroll
    for (int k = 0; k < EDf; k++)
        w[k] = *(const float2*)(We_l + k * Hh + colb);
    const float2 bev = *(const float2*)(be_l + colb);

    const int is64 = g_flags[0];
    const long long* ei64 = (const long long*)ei;
    const int*       ei32 = (const int*)ei;

    for (int chunk = blockIdx.x * 128; chunk < Ee; chunk += gridDim.x * 128) {
        __syncthreads();
        for (int i = tid; i < 128 * EDf / 4; i += 256)
            ((float4*)s_ea)[i] = *(const float4*)(ea + (size_t)chunk * EDf + i * 4);
        if (tid < 128) {
            s_src[tid] = is64 ? (int)ei64[chunk + tid] : ei32[chunk + tid];
            s_dst[tid] = is64 ? (int)ei64[Ee + chunk + tid] : ei32[Ee + chunk + tid];
        }
        __syncthreads();
        for (int eo = warp; eo < 128; eo += 16) {
            const int e1 = eo + 8;
            int s0 = s_src[eo], d0 = s_dst[eo];
            int s1 = s_src[e1], d1 = s_dst[e1];
            // issue both gathers before the FMA chains
            float2 h0 = *(const float2*)(hid + (size_t)s0 * Hh + colb);
            float2 h1 = *(const float2*)(hid + (size_t)s1 * Hh + colb);
            float2 a0 = bev, a1 = bev;
#pragma unroll
            for (int k = 0; k < EDf; k++) {
                float v0 = s_ea[eo * EDf + k];
                float v1 = s_ea[e1 * EDf + k];
                a0.x += v0 * w[k].x; a0.y += v0 * w[k].y;
                a1.x += v1 * w[k].x; a1.y += v1 * w[k].y;
            }
            float m0x = fmaxf(h0.x + a0.x, 0.f);
            float m0y = fmaxf(h0.y + a0.y, 0.f);
            float m1x = fmaxf(h1.x + a1.x, 0.f);
            float m1y = fmaxf(h1.y + a1.y, 0.f);
            float* p0 = agg + (size_t)d0 * Hh + colb;
            float* p1 = agg + (size_t)d1 * Hh + colb;
            asm volatile("red.global.add.v2.f32 [%0], {%1,%2};"
                         :: "l"(p0), "f"(m0x), "f"(m0y) : "memory");
            asm volatile("red.global.add.v2.f32 [%0], {%1,%2};"
                         :: "l"(p1), "f"(m1x), "f"(m1y) : "memory");
        }
    }
}

// ---------------- host ----------------
extern "C" void kernel_launch(void* const* d_in, const int* in_sizes, int n_in,
                              void* d_out, int out_size)
{
    const float *x = nullptr, *ea = nullptr, *Wnh = nullptr, *bnh = nullptr;
    const float *W1 = nullptr, *b1 = nullptr, *We = nullptr, *be = nullptr;
    const float *Wl1 = nullptr, *bl1 = nullptr, *Wl2 = nullptr, *bl2 = nullptr;
    const void *ei = nullptr, *batch = nullptr;
    int c256 = 0, c131 = 0;

    for (int i = 0; i < n_in; i++) {
        const void* p = d_in[i];
        switch (in_sizes[i]) {
            case 7864320:  x   = (const float*)p; break;          // x [N,30]
            case 13631488: ea  = (const float*)p; break;          // edge_attr [E,13]
            case 2097152:  ei  = p; break;                        // edge_index [2,E]
            case 262144:   batch = p; break;                      // batch [N]
            case 7680:     Wnh = (const float*)p; break;          // [30,256]
            case 65536:    W1  = (const float*)p; break;          // [256,256]
            case 13312:    We  = (const float*)p; break;          // [4,13,256]
            case 1024:     be  = (const float*)p; break;          // [4,256]
            case 512:      bl1 = (const float*)p; break;          // [512]
            case 131072:   if (c131++ == 0) Wl1 = (const float*)p;
                           else             Wl2 = (const float*)p; break;
            case 256:      if (c256 == 0)      bnh = (const float*)p;
                           else if (c256 == 1) b1  = (const float*)p;
                           else                bl2 = (const float*)p;
                           c256++; break;
            default: break;
        }
    }

    float *hid, *hid2, *aggA, *aggB, *Zp, *cnt, *ea_s;
    void *eis;
    cudaGetSymbolAddress((void**)&hid,  g_hid);
    cudaGetSymbolAddress((void**)&hid2, g_hid2);
    cudaGetSymbolAddress((void**)&aggA, g_agg);
    cudaGetSymbolAddress((void**)&aggB, g_aggB);
    cudaGetSymbolAddress((void**)&Zp,   g_Z);
    cudaGetSymbolAddress((void**)&cnt,  g_cnt);
    cudaGetSymbolAddress((void**)&ea_s, g_ea_s);
    cudaGetSymbolAddress(&eis,          g_eis);

    const int smem_pipe = (2 * 4608 + 2 * 4224) * 4;   // 70656 B
    cudaFuncSetAttribute(gemm_pipe<true,  true, false>,
                         cudaFuncAttributeMaxDynamicSharedMemorySize, smem_pipe);
    cudaFuncSetAttribute(gemm_pipe<false, true, false>,
                         cudaFuncAttributeMaxDynamicSharedMemorySize, smem_pipe);
    cudaFuncSetAttribute(gemm_pipe<false, true, true>,
                         cudaFuncAttributeMaxDynamicSharedMemorySize, smem_pipe);

    detect_kernel<<<1, 32>>>((const unsigned*)ei, (const unsigned*)batch);
    // src-sort the edge stream (gather locality); kernel body stays frozen
    conv_ei_kernel<<<2048, 256>>>(ei);
    hist_zero_kernel<<<512, 256>>>();
    hist_kernel<<<2048, 256>>>();
    scan_kernel<<<1, 1024>>>();
    scatter_kernel<<<2048, 256>>>();
    ea_copy_kernel<<<2048, 256>>>(ea);

    b32_kernel<<<512, 256>>>(batch);
    cnt_kernel<<<Gg / 256, 256>>>();
    // zero the pooled accumulator Z (16 MB; L2-resident during lin1)
    zero_kernel<<<256, 256>>>((float4*)Zp, Gg * GHh / 4);

    // hid = x @ W_nh + b_nh ; seed aggA = hid  (layer 0 pre-seed)
    gemm_tf32<false, false, true><<<dim3(2, Nn / 128), 256>>>(
        x, Wnh, bnh, nullptr, hid, aggA, Nn, Hh, NCf, NCf);

    float* cur = hid;
    float* nxt = hid2;
    float* agg_cur = aggA;
    float* agg_nxt = aggB;
    for (int l = 0; l < 4; l++) {
        // agg_cur (pre-seeded with hid) += sum of relu(hid[src]+e) per dst
        edge_kernel<<<dim3(592, 4), 256>>>(ea_s, eis, We + (size_t)l * EDf * Hh,
                                           be + (size_t)l * Hh, cur, agg_cur);
        // hid' = relu(agg_cur @ W1 + b1); seed agg_nxt = hid' for next layer
        if (l < 3)
            gemm_pipe<true, true, false><<<dim3(2, Nn / 128), 256, smem_pipe>>>(
                agg_cur, W1, b1, nxt, agg_nxt, Nn, Hh, Hh);
        else
            gemm_pipe<false, true, false><<<dim3(2, Nn / 128), 256, smem_pipe>>>(
                agg_cur, W1, b1, nxt, nullptr, Nn, Hh, Hh);
        float* t = cur; cur = nxt; nxt = t;
        t = agg_cur; agg_cur = agg_nxt; agg_nxt = t;
    }

    // Z[g] += relu(hid @ Wl1 + bl1) rows pooled by graph (fused epilogue)
    gemm_pipe<false, true, true><<<dim3(4, Nn / 128), 256, smem_pipe>>>(
        cur, Wl1, bl1, nullptr, nullptr, Nn, GHh, Hh);

    // out = Z @ Wl2 + cnt * bl2   (lin2 commutes with segment_sum)
    gemm_tf32<false, true, false><<<dim3(2, Gg / 128), 256>>>(
        Zp, Wl2, bl2, cnt, (float*)d_out, nullptr, Gg, OUTC, GHh, GHh);
}

// round 15
// speedup vs baseline: 1.1353x; 1.1353x over previous
#include <cuda_runtime.h>
#include <cstdint>

#define Nn   262144
#define Ee   1048576
#define NCf  30
#define EDf  13
#define Hh   256
#define GHh  512
#define OUTC 256
#define Gg   8192

// ---------------- device scratch (no allocs allowed) ----------------
__device__ float g_hid [(size_t)Nn * Hh];
__device__ float g_hid2[(size_t)Nn * Hh];
__device__ float g_agg [(size_t)Nn * Hh];   // agg ping
__device__ float g_aggB[(size_t)Nn * Hh];   // agg pong
__device__ float g_Z   [(size_t)Gg * GHh];
__device__ float g_cnt [Gg];
__device__ int   g_b32 [Nn];
__device__ int   g_flags[2];   // [0]=edge_index is int64, [1]=batch is int64

// ---------------- helpers ----------------
__device__ __forceinline__ unsigned f2tf(float x) {
    unsigned r;
    asm("cvt.rna.tf32.f32 %0, %1;" : "=r"(r) : "f"(x));
    return r;
}
__device__ __forceinline__ void cpa16(float* s, const float* g) {
    unsigned sa = (unsigned)__cvta_generic_to_shared(s);
    asm volatile("cp.async.cg.shared.global [%0], [%1], 16;\n" :: "r"(sa), "l"(g));
}

// dtype detection: int64 little-endian high words (odd 32-bit indices) are 0 for
// values < 2^31; int32 payloads at the buffer tail are nonzero with ~certainty.
__global__ void detect_kernel(const unsigned* __restrict__ ei,
                              const unsigned* __restrict__ bt) {
    if (threadIdx.x == 0 && blockIdx.x == 0) {
        int is64 = 1;
        for (int i = 0; i < 8; i++)
            if (ei[2 * Ee - 1 - 2 * i] != 0u) is64 = 0;   // odd indices
        g_flags[0] = is64;
        int b64 = 1;
        for (int i = 0; i < 8; i++)
            if (bt[Nn - 1 - 2 * i] != 0u) b64 = 0;        // Nn-1 is odd
        g_flags[1] = b64;
    }
}

__global__ void zero_kernel(float4* __restrict__ p, int n4) {
    for (int i = blockIdx.x * blockDim.x + threadIdx.x; i < n4;
         i += gridDim.x * blockDim.x)
        p[i] = make_float4(0.f, 0.f, 0.f, 0.f);
}

// batch -> int32 (once per replay; cheap)
__global__ void b32_kernel(const void* __restrict__ batch) {
    const int is64 = g_flags[1];
    const long long* b64 = (const long long*)batch;
    const int*       b32 = (const int*)batch;
    for (int i = blockIdx.x * blockDim.x + threadIdx.x; i < Nn;
         i += gridDim.x * blockDim.x)
        g_b32[i] = is64 ? (int)b64[i] : b32[i];
}

// cnt[g] = |graph g| via binary search on sorted batch32
__global__ void cnt_kernel() {
    const int g = blockIdx.x * blockDim.x + threadIdx.x;
    if (g >= Gg) return;
    int lo = 0, hi = Nn;
    while (lo < hi) {
        int mid = (lo + hi) >> 1;
        if (g_b32[mid] < g) lo = mid + 1; else hi = mid;
    }
    const int start = lo;
    hi = Nn;
    while (lo < hi) {
        int mid = (lo + hi) >> 1;
        if (g_b32[mid] < g + 1) lo = mid + 1; else hi = mid;
    }
    g_cnt[g] = (float)(lo - start);
}

// ==================================================================
// Pipelined tf32 GEMM: 3-stage cp.async buffer (issue 2 tiles ahead).
// C[M,Nc] = relu?(A @ B + bias). lda == K, K % 32 == 0.
// CTA tile 128x128, 8 warps. x = N-tile (fast), y = M-tile.
// SEED: also store the epilogue values into zbuf (seeds next layer's agg).
// POOL: red.add the values into Z[batch32[row]*Nc+col] instead of storing C.
// smem: 3*(4608 + 4224) floats = 105984 B -> still 2 CTAs/SM.
// ==================================================================
template <bool SEED, bool RELU, bool POOL>
__global__ __launch_bounds__(256, 2)
void gemm_pipe(const float* __restrict__ A, const float* __restrict__ B,
               const float* __restrict__ bias, float* __restrict__ C,
               float* __restrict__ zbuf, int M, int Nc, int K)
{
    extern __shared__ float sm[];
    float* As = sm;                  // 3 * 4608
    float* Bs = sm + 3 * 4608;       // 3 * 4224

    const int tid   = threadIdx.x;
    const int lane  = tid & 31;
    const int warp  = tid >> 5;
    const int tq    = lane & 3;
    const int gq    = lane >> 2;
    const int warpM = (warp & 3) * 32;
    const int warpN = (warp >> 2) * 64;
    const int blockM = blockIdx.y * 128;
    const int blockN = blockIdx.x * 128;

    float acc[2][8][4];
#pragma unroll
    for (int mt = 0; mt < 2; mt++)
#pragma unroll
        for (int nt = 0; nt < 8; nt++)
#pragma unroll
            for (int j = 0; j < 4; j++) acc[mt][nt][j] = 0.f;

    auto issue = [&](int k0, int st) {
#pragma unroll
        for (int i = 0; i < 4; i++) {
            int idx = tid + i * 256;
            int row = idx >> 3;
            int c   = (idx & 7) * 4;
            cpa16(As + st * 4608 + row * 36 + c,
                  A + (size_t)(blockM + row) * K + k0 + c);
        }
#pragma unroll
        for (int i = 0; i < 4; i++) {
            int idx = tid + i * 256;
            int row = idx >> 5;
            int c   = (idx & 31) * 4;
            cpa16(Bs + st * 4224 + row * 132 + c,
                  B + (size_t)(k0 + row) * Nc + blockN + c);
        }
        asm volatile("cp.async.commit_group;\n" ::: "memory");
    };

    const int nIter = K >> 5;
    issue(0, 0);
    if (nIter > 1) issue(32, 1);

    for (int it = 0; it < nIter; it++) {
        const int st = it % 3;
        if (it + 2 < nIter) {
            issue((it + 2) << 5, (it + 2) % 3);
            asm volatile("cp.async.wait_group 2;\n" ::: "memory");
        } else if (it + 1 < nIter) {
            asm volatile("cp.async.wait_group 1;\n" ::: "memory");
        } else {
            asm volatile("cp.async.wait_group 0;\n" ::: "memory");
        }
        __syncthreads();

        const float* as = As + st * 4608;
        const float* bs = Bs + st * 4224;
#pragma unroll
        for (int kk = 0; kk < 32; kk += 8) {
            unsigned a[2][4], b[8][2];
#pragma unroll
            for (int mt = 0; mt < 2; mt++) {
                int r = warpM + mt * 16 + gq;
                a[mt][0] = f2tf(as[(r)     * 36 + kk + tq]);
                a[mt][1] = f2tf(as[(r + 8) * 36 + kk + tq]);
                a[mt][2] = f2tf(as[(r)     * 36 + kk + tq + 4]);
                a[mt][3] = f2tf(as[(r + 8) * 36 + kk + tq + 4]);
            }
#pragma unroll
            for (int nt = 0; nt < 8; nt++) {
                int cidx = warpN + nt * 8 + gq;
                b[nt][0] = f2tf(bs[(kk + tq)     * 132 + cidx]);
                b[nt][1] = f2tf(bs[(kk + tq + 4) * 132 + cidx]);
            }
#pragma unroll
            for (int mt = 0; mt < 2; mt++)
#pragma unroll
                for (int nt = 0; nt < 8; nt++)
                    asm volatile(
                        "mma.sync.aligned.m16n8k8.row.col.f32.tf32.tf32.f32 "
                        "{%0,%1,%2,%3},{%4,%5,%6,%7},{%8,%9},{%0,%1,%2,%3};"
                        : "+f"(acc[mt][nt][0]), "+f"(acc[mt][nt][1]),
                          "+f"(acc[mt][nt][2]), "+f"(acc[mt][nt][3])
                        : "r"(a[mt][0]), "r"(a[mt][1]), "r"(a[mt][2]),
                          "r"(a[mt][3]), "r"(b[nt][0]), "r"(b[nt][1]));
        }
        __syncthreads();
    }

#pragma unroll
    for (int mt = 0; mt < 2; mt++) {
        int r0 = blockM + warpM + mt * 16 + gq;
        int r1 = r0 + 8;
        int zg0 = 0, zg1 = 0;
        if (POOL) { zg0 = g_b32[r0]; zg1 = g_b32[r1]; }
#pragma unroll
        for (int nt = 0; nt < 8; nt++) {
            int col = blockN + warpN + nt * 8 + 2 * tq;
            float b0 = bias[col], b1 = bias[col + 1];
            float v0 = acc[mt][nt][0] + b0, v1 = acc[mt][nt][1] + b1;
            float v2 = acc[mt][nt][2] + b0, v3 = acc[mt][nt][3] + b1;
            if (RELU) {
                v0 = fmaxf(v0, 0.f); v1 = fmaxf(v1, 0.f);
                v2 = fmaxf(v2, 0.f); v3 = fmaxf(v3, 0.f);
            }
            if (POOL) {
                float* q0 = g_Z + (size_t)zg0 * GHh + col;
                float* q1 = g_Z + (size_t)zg1 * GHh + col;
                asm volatile("red.global.add.v2.f32 [%0], {%1,%2};"
                             :: "l"(q0), "f"(v0), "f"(v1) : "memory");
                asm volatile("red.global.add.v2.f32 [%0], {%1,%2};"
                             :: "l"(q1), "f"(v2), "f"(v3) : "memory");
            } else {
                *(float2*)(C + (size_t)r0 * Nc + col) = make_float2(v0, v1);
                *(float2*)(C + (size_t)r1 * Nc + col) = make_float2(v2, v3);
                if (SEED) {
                    *(float2*)(zbuf + (size_t)r0 * Nc + col) = make_float2(v0, v1);
                    *(float2*)(zbuf + (size_t)r1 * Nc + col) = make_float2(v2, v3);
                }
            }
        }
    }
}

// ==================================================================
// Single-buffered tf32 GEMM — embed (K=30, unaligned rows; SEED seeds aggA
// with hid) and the final small GEMM (CNTB).
// x = N-tile, y = M-tile.
// ==================================================================
template <bool RELU, bool CNTB, bool SEED>
__global__ __launch_bounds__(256)
void gemm_tf32(const float* __restrict__ A, const float* __restrict__ B,
               const float* __restrict__ bias, const float* __restrict__ cnt,
               float* __restrict__ C, float* __restrict__ zbuf,
               int M, int Nc, int K, int lda)
{
    __shared__ unsigned As[128][36];
    __shared__ unsigned Bs[32][132];

    const int tid   = threadIdx.x;
    const int lane  = tid & 31;
    const int warp  = tid >> 5;
    const int tq    = lane & 3;
    const int gq    = lane >> 2;
    const int warpM = (warp & 3) * 32;
    const int warpN = (warp >> 2) * 64;
    const int blockM = blockIdx.y * 128;
    const int blockN = blockIdx.x * 128;

    float acc[2][8][4];
#pragma unroll
    for (int mt = 0; mt < 2; mt++)
#pragma unroll
        for (int nt = 0; nt < 8; nt++)
#pragma unroll
            for (int j = 0; j < 4; j++) acc[mt][nt][j] = 0.f;

    for (int k0 = 0; k0 < K; k0 += 32) {
        __syncthreads();
        const bool v4 = ((lda & 3) == 0) && (k0 + 32 <= K);
#pragma unroll
        for (int i = 0; i < 4; i++) {
            int row = (tid >> 3) + i * 32;
            int kq  = (tid & 7) * 4;
            size_t base = (size_t)(blockM + row) * lda + k0 + kq;
            float v0, v1, v2, v3;
            if (v4) {
                float4 tv = *(const float4*)(A + base);
                v0 = tv.x; v1 = tv.y; v2 = tv.z; v3 = tv.w;
            } else {
                v0 = (k0 + kq + 0 < K) ? A[base + 0] : 0.f;
                v1 = (k0 + kq + 1 < K) ? A[base + 1] : 0.f;
                v2 = (k0 + kq + 2 < K) ? A[base + 2] : 0.f;
                v3 = (k0 + kq + 3 < K) ? A[base + 3] : 0.f;
            }
            As[row][kq + 0] = f2tf(v0);
            As[row][kq + 1] = f2tf(v1);
            As[row][kq + 2] = f2tf(v2);
            As[row][kq + 3] = f2tf(v3);
        }
#pragma unroll
        for (int i = 0; i < 4; i++) {
            int kr = (tid >> 5) + i * 8;
            int n4 = (tid & 31) * 4;
            float4 tv = make_float4(0.f, 0.f, 0.f, 0.f);
            if (k0 + kr < K)
                tv = *(const float4*)(B + (size_t)(k0 + kr) * Nc + blockN + n4);
            Bs[kr][n4 + 0] = f2tf(tv.x);
            Bs[kr][n4 + 1] = f2tf(tv.y);
            Bs[kr][n4 + 2] = f2tf(tv.z);
            Bs[kr][n4 + 3] = f2tf(tv.w);
        }
        __syncthreads();
#pragma unroll
        for (int kk = 0; kk < 32; kk += 8) {
            unsigned a[2][4], b[8][2];
#pragma unroll
            for (int mt = 0; mt < 2; mt++) {
                int r = warpM + mt * 16;
                a[mt][0] = As[r + gq][kk + tq];
                a[mt][1] = As[r + gq + 8][kk + tq];
                a[mt][2] = As[r + gq][kk + tq + 4];
                a[mt][3] = As[r + gq + 8][kk + tq + 4];
            }
#pragma unroll
            for (int nt = 0; nt < 8; nt++) {
                int cidx = warpN + nt * 8 + gq;
                b[nt][0] = Bs[kk + tq][cidx];
                b[nt][1] = Bs[kk + tq + 4][cidx];
            }
#pragma unroll
            for (int mt = 0; mt < 2; mt++)
#pragma unroll
                for (int nt = 0; nt < 8; nt++)
                    asm volatile(
                        "mma.sync.aligned.m16n8k8.row.col.f32.tf32.tf32.f32 "
                        "{%0,%1,%2,%3},{%4,%5,%6,%7},{%8,%9},{%0,%1,%2,%3};"
                        : "+f"(acc[mt][nt][0]), "+f"(acc[mt][nt][1]),
                          "+f"(acc[mt][nt][2]), "+f"(acc[mt][nt][3])
                        : "r"(a[mt][0]), "r"(a[mt][1]), "r"(a[mt][2]),
                          "r"(a[mt][3]), "r"(b[nt][0]), "r"(b[nt][1]));
        }
    }
#pragma unroll
    for (int mt = 0; mt < 2; mt++) {
        int r0 = blockM + warpM + mt * 16 + gq;
        int r1 = r0 + 8;
        float cn0 = 0.f, cn1 = 0.f;
        if (CNTB) { cn0 = cnt[r0]; cn1 = cnt[r1]; }
#pragma unroll
        for (int nt = 0; nt < 8; nt++) {
            int col = blockN + warpN + nt * 8 + 2 * tq;
            float b0 = bias[col], b1 = bias[col + 1];
            float v0 = acc[mt][nt][0], v1 = acc[mt][nt][1];
            float v2 = acc[mt][nt][2], v3 = acc[mt][nt][3];
            if (CNTB) { v0 += cn0 * b0; v1 += cn0 * b1; v2 += cn1 * b0; v3 += cn1 * b1; }
            else      { v0 += b0;       v1 += b1;       v2 += b0;       v3 += b1; }
            if (RELU) {
                v0 = fmaxf(v0, 0.f); v1 = fmaxf(v1, 0.f);
                v2 = fmaxf(v2, 0.f); v3 = fmaxf(v3, 0.f);
            }
            *(float2*)(C + (size_t)r0 * Nc + col) = make_float2(v0, v1);
            *(float2*)(C + (size_t)r1 * Nc + col) = make_float2(v2, v3);
            if (SEED) {
                *(float2*)(zbuf + (size_t)r0 * Nc + col) = make_float2(v0, v1);
                *(float2*)(zbuf + (size_t)r1 * Nc + col) = make_float2(v2, v3);
            }
        }
    }
}

// ==================================================================
// Edge kernel — EXACT R13 source (frozen; proven 423us/layer): 64-col passes
// (gridDim.y=4), float2 weight bank, 2 edges per warp-iter, is64 selects.
// e = ea@We[l]+be[l]; msg = relu(hid[src]+e); red.add.v2 into agg[dst].
// agg is pre-seeded with hid, so after this kernel agg = hid + sum(msg).
// ==================================================================
__global__ __launch_bounds__(256)
void edge_kernel(const float* __restrict__ ea, const void* __restrict__ ei,
                 const float* __restrict__ We_l, const float* __restrict__ be_l,
                 const float* __restrict__ hid, float* __restrict__ agg)
{
    __shared__ float s_ea[128 * EDf];
    __shared__ int   s_src[128], s_dst[128];

    const int tid  = threadIdx.x;
    const int lane = tid & 31;
    const int warp = tid >> 5;
    const int colb = blockIdx.y * 64 + lane * 2;

    float2 w[EDf];
#pragma unroll
    for (int k = 0; k < EDf; k++)
        w[k] = *(const float2*)(We_l + k * Hh + colb);
    const float2 bev = *(const float2*)(be_l + colb);

    const int is64 = g_flags[0];
    const long long* ei64 = (const long long*)ei;
    const int*       ei32 = (const int*)ei;

    for (int chunk = blockIdx.x * 128; chunk < Ee; chunk += gridDim.x * 128) {
        __syncthreads();
        for (int i = tid; i < 128 * EDf / 4; i += 256)
            ((float4*)s_ea)[i] = *(const float4*)(ea + (size_t)chunk * EDf + i * 4);
        if (tid < 128) {
            s_src[tid] = is64 ? (int)ei64[chunk + tid] : ei32[chunk + tid];
            s_dst[tid] = is64 ? (int)ei64[Ee + chunk + tid] : ei32[Ee + chunk + tid];
        }
        __syncthreads();
        for (int eo = warp; eo < 128; eo += 16) {
            const int e1 = eo + 8;
            int s0 = s_src[eo], d0 = s_dst[eo];
            int s1 = s_src[e1], d1 = s_dst[e1];
            // issue both gathers before the FMA chains
            float2 h0 = *(const float2*)(hid + (size_t)s0 * Hh + colb);
            float2 h1 = *(const float2*)(hid + (size_t)s1 * Hh + colb);
            float2 a0 = bev, a1 = bev;
#pragma unroll
            for (int k = 0; k < EDf; k++) {
                float v0 = s_ea[eo * EDf + k];
                float v1 = s_ea[e1 * EDf + k];
                a0.x += v0 * w[k].x; a0.y += v0 * w[k].y;
                a1.x += v1 * w[k].x; a1.y += v1 * w[k].y;
            }
            float m0x = fmaxf(h0.x + a0.x, 0.f);
            float m0y = fmaxf(h0.y + a0.y, 0.f);
            float m1x = fmaxf(h1.x + a1.x, 0.f);
            float m1y = fmaxf(h1.y + a1.y, 0.f);
            float* p0 = agg + (size_t)d0 * Hh + colb;
            float* p1 = agg + (size_t)d1 * Hh + colb;
            asm volatile("red.global.add.v2.f32 [%0], {%1,%2};"
                         :: "l"(p0), "f"(m0x), "f"(m0y) : "memory");
            asm volatile("red.global.add.v2.f32 [%0], {%1,%2};"
                         :: "l"(p1), "f"(m1x), "f"(m1y) : "memory");
        }
    }
}

// ---------------- host ----------------
extern "C" void kernel_launch(void* const* d_in, const int* in_sizes, int n_in,
                              void* d_out, int out_size)
{
    const float *x = nullptr, *ea = nullptr, *Wnh = nullptr, *bnh = nullptr;
    const float *W1 = nullptr, *b1 = nullptr, *We = nullptr, *be = nullptr;
    const float *Wl1 = nullptr, *bl1 = nullptr, *Wl2 = nullptr, *bl2 = nullptr;
    const void *ei = nullptr, *batch = nullptr;
    int c256 = 0, c131 = 0;

    for (int i = 0; i < n_in; i++) {
        const void* p = d_in[i];
        switch (in_sizes[i]) {
            case 7864320:  x   = (const float*)p; break;          // x [N,30]
            case 13631488: ea  = (const float*)p; break;          // edge_attr [E,13]
            case 2097152:  ei  = p; break;                        // edge_index [2,E]
            case 262144:   batch = p; break;                      // batch [N]
            case 7680:     Wnh = (const float*)p; break;          // [30,256]
            case 65536:    W1  = (const float*)p; break;          // [256,256]
            case 13312:    We  = (const float*)p; break;          // [4,13,256]
            case 1024:     be  = (const float*)p; break;          // [4,256]
            case 512:      bl1 = (const float*)p; break;          // [512]
            case 131072:   if (c131++ == 0) Wl1 = (const float*)p;
                           else             Wl2 = (const float*)p; break;
            case 256:      if (c256 == 0)      bnh = (const float*)p;
                           else if (c256 == 1) b1  = (const float*)p;
                           else                bl2 = (const float*)p;
                           c256++; break;
            default: break;
        }
    }

    float *hid, *hid2, *aggA, *aggB, *Zp, *cnt;
    cudaGetSymbolAddress((void**)&hid,  g_hid);
    cudaGetSymbolAddress((void**)&hid2, g_hid2);
    cudaGetSymbolAddress((void**)&aggA, g_agg);
    cudaGetSymbolAddress((void**)&aggB, g_aggB);
    cudaGetSymbolAddress((void**)&Zp,   g_Z);
    cudaGetSymbolAddress((void**)&cnt,  g_cnt);

    const int smem_pipe = (3 * 4608 + 3 * 4224) * 4;   // 105984 B
    cudaFuncSetAttribute(gemm_pipe<true,  true, false>,
                         cudaFuncAttributeMaxDynamicSharedMemorySize, smem_pipe);
    cudaFuncSetAttribute(gemm_pipe<false, true, false>,
                         cudaFuncAttributeMaxDynamicSharedMemorySize, smem_pipe);
    cudaFuncSetAttribute(gemm_pipe<false, true, true>,
                         cudaFuncAttributeMaxDynamicSharedMemorySize, smem_pipe);

    detect_kernel<<<1, 32>>>((const unsigned*)ei, (const unsigned*)batch);
    b32_kernel<<<512, 256>>>(batch);
    cnt_kernel<<<Gg / 256, 256>>>();
    // zero the pooled accumulator Z (16 MB; L2-resident during lin1)
    zero_kernel<<<256, 256>>>((float4*)Zp, Gg * GHh / 4);

    // hid = x @ W_nh + b_nh ; seed aggA = hid  (layer 0 pre-seed)
    gemm_tf32<false, false, true><<<dim3(2, Nn / 128), 256>>>(
        x, Wnh, bnh, nullptr, hid, aggA, Nn, Hh, NCf, NCf);

    float* cur = hid;
    float* nxt = hid2;
    float* agg_cur = aggA;
    float* agg_nxt = aggB;
    for (int l = 0; l < 4; l++) {
        // agg_cur (pre-seeded with hid) += sum of relu(hid[src]+e) per dst
        edge_kernel<<<dim3(592, 4), 256>>>(ea, ei, We + (size_t)l * EDf * Hh,
                                           be + (size_t)l * Hh, cur, agg_cur);
        // hid' = relu(agg_cur @ W1 + b1); seed agg_nxt = hid' for next layer
        if (l < 3)
            gemm_pipe<true, true, false><<<dim3(2, Nn / 128), 256, smem_pipe>>>(
                agg_cur, W1, b1, nxt, agg_nxt, Nn, Hh, Hh);
        else
            gemm_pipe<false, true, false><<<dim3(2, Nn / 128), 256, smem_pipe>>>(
                agg_cur, W1, b1, nxt, nullptr, Nn, Hh, Hh);
        float* t = cur; cur = nxt; nxt = t;
        t = agg_cur; agg_cur = agg_nxt; agg_nxt = t;
    }

    // Z[g] += relu(hid @ Wl1 + bl1) rows pooled by graph (fused epilogue)
    gemm_pipe<false, true, true><<<dim3(4, Nn / 128), 256, smem_pipe>>>(
        cur, Wl1, bl1, nullptr, nullptr, Nn, GHh, Hh);

    // out = Z @ Wl2 + cnt * bl2   (lin2 commutes with segment_sum)
    gemm_tf32<false, true, false><<<dim3(2, Gg / 128), 256>>>(
        Zp, Wl2, bl2, cnt, (float*)d_out, nullptr, Gg, OUTC, GHh, GHh);
}